// round 16
// baseline (speedup 1.0000x reference)
#include <cuda_runtime.h>
#include <cuda_bf16.h>
#include <math.h>
#include <stdint.h>

// ---------------------------------------------------------------------------
// Problem dims (fixed)
// ---------------------------------------------------------------------------
#define T_   2048
#define D_   1024
#define H_   16
#define HD_  64
#define NH_  2
#define STEPS (T_*NH_)          // 4096
#define ROW  (H_*HD_)           // 1024
#define SPAD (STEPS + 8)
#define GSTEPS 8
#define NSLOT 8
#define LOOKA 7
#define NGRP8 (STEPS/GSTEPS)

// ---------------------------------------------------------------------------
// Scratch (static device memory; allocation-free).
// ---------------------------------------------------------------------------
__device__ __align__(256) float g_qbuf[(T_ + 4) * ROW];
__device__ __align__(256) float g_kbuf[SPAD * ROW];
__device__ __align__(256) float g_vbuf[SPAD * ROW];
__device__ __align__(256) float g_gbuf[T_ * ROW];
__device__ __align__(256) float g_bbuf[T_ * (NH_ * H_)];
__device__ __align__(256) float g_abuf[T_ * H_];
__device__ __align__(256) float g_betab[H_ * SPAD];
__device__ __align__(256) float g_decb[H_ * SPAD];
__device__ __align__(256) float g_obuf[T_ * ROW];

// bf16 split buffers (hi/lo), weights transposed to [N][K]
__device__ __align__(256) __nv_bfloat16 g_xh[T_ * D_],    g_xl[T_ * D_];
__device__ __align__(256) __nv_bfloat16 g_oh[T_ * ROW],   g_ol[T_ * ROW];
__device__ __align__(256) __nv_bfloat16 g_wqh[1024 * D_], g_wql[1024 * D_];
__device__ __align__(256) __nv_bfloat16 g_wkh[2048 * D_], g_wkl[2048 * D_];
__device__ __align__(256) __nv_bfloat16 g_wvh[2048 * D_], g_wvl[2048 * D_];
__device__ __align__(256) __nv_bfloat16 g_wgh[1024 * D_], g_wgl[1024 * D_];
__device__ __align__(256) __nv_bfloat16 g_woh[1024 * ROW], g_wol[1024 * ROW];

// ---------------------------------------------------------------------------
// f32x2 packed helpers
// ---------------------------------------------------------------------------
typedef unsigned long long ull;

__device__ __forceinline__ void fma2(ull& d, ull a, ull b) {
    asm("fma.rn.f32x2 %0, %1, %2, %3;" : "=l"(d) : "l"(a), "l"(b), "l"(d));
}
__device__ __forceinline__ void add2(ull& d, ull a, ull b) {
    asm("add.rn.f32x2 %0, %1, %2;" : "=l"(d) : "l"(a), "l"(b));
}
__device__ __forceinline__ ull mul2(ull a, ull b) {
    ull d;
    asm("mul.rn.f32x2 %0, %1, %2;" : "=l"(d) : "l"(a), "l"(b));
    return d;
}
__device__ __forceinline__ ull pk2(float x, float y) {
    ull r;
    asm("mov.b64 %0, {%1, %2};" : "=l"(r)
        : "r"(__float_as_uint(x)), "r"(__float_as_uint(y)));
    return r;
}
__device__ __forceinline__ void up2(ull v, float& lo, float& hi) {
    unsigned a, b;
    asm("mov.b64 {%0, %1}, %2;" : "=r"(a), "=r"(b) : "l"(v));
    lo = __uint_as_float(a); hi = __uint_as_float(b);
}

// ---------------------------------------------------------------------------
// cp.async helpers (16 BYTES per op)
// ---------------------------------------------------------------------------
__device__ __forceinline__ void cpasync16(void* dst, const void* src) {
    unsigned d = (unsigned)__cvta_generic_to_shared(dst);
    asm volatile("cp.async.cg.shared.global [%0], [%1], 16;" :: "r"(d), "l"(src));
}
#define CP_COMMIT() asm volatile("cp.async.commit_group;")
#define CP_WAIT(n)  asm volatile("cp.async.wait_group %0;" :: "n"(n))

__device__ __forceinline__ uint32_t smem_u32(const void* p) {
    uint32_t a;
    asm("{ .reg .u64 t; cvta.to.shared.u64 t, %1; cvt.u32.u64 %0, t; }"
        : "=r"(a) : "l"(p));
    return a;
}

// ---------------------------------------------------------------------------
// warp-MMA primitives
// ---------------------------------------------------------------------------
__device__ __forceinline__ void ldsm4(uint32_t addr, uint32_t* r) {
    asm volatile("ldmatrix.sync.aligned.m8n8.x4.shared.b16 {%0,%1,%2,%3}, [%4];"
        : "=r"(r[0]), "=r"(r[1]), "=r"(r[2]), "=r"(r[3]) : "r"(addr));
}
__device__ __forceinline__ void mma16816(float* d, const uint32_t* a, const uint32_t* b) {
    asm volatile(
        "mma.sync.aligned.m16n8k16.row.col.f32.bf16.bf16.f32 "
        "{%0,%1,%2,%3}, {%4,%5,%6,%7}, {%8,%9}, {%0,%1,%2,%3};"
        : "+f"(d[0]), "+f"(d[1]), "+f"(d[2]), "+f"(d[3])
        : "r"(a[0]), "r"(a[1]), "r"(a[2]), "r"(a[3]), "r"(b[0]), "r"(b[1]));
}

// ---------------------------------------------------------------------------
// Warp-MMA GEMM (R8-proven, unchanged): 128x128 CTA tile, 256 threads.
// ---------------------------------------------------------------------------
#define KC    32
#define AST   40
#define TILEE (128 * AST)
#define MM_SMEM (2 * 4 * TILEE * 2)   // 81920 B

__device__ __forceinline__ void mm_load_tile(
    __nv_bfloat16* dst, const __nv_bfloat16* src, int row0, int K, int k0, int tid)
{
#pragma unroll
    for (int i = 0; i < 2; i++) {
        int c0 = tid + i * 256;
        int r = c0 >> 2, c = c0 & 3;
        cpasync16(dst + r * AST + c * 8, src + (size_t)(row0 + r) * K + k0 + c * 8);
    }
}

__global__ void __launch_bounds__(256) mm_wmma_kernel(
    const __nv_bfloat16* __restrict__ Ah, const __nv_bfloat16* __restrict__ Al,
    const __nv_bfloat16* __restrict__ Bh, const __nv_bfloat16* __restrict__ Bl,
    float* __restrict__ C, int M, int N, int K)
{
    extern __shared__ __nv_bfloat16 sm[];
    const uint32_t sbase = smem_u32(sm);
    const int tid = threadIdx.x;
    const int wid = tid >> 5;
    const int lane = tid & 31;
    const int rowC = blockIdx.y * 128;
    const int colC = blockIdx.x * 128;
    const int wr = wid >> 2;
    const int wc = wid & 3;
    const int m0w = wr * 64;
    const int n0w = wc * 32;

    const int arow = lane & 15;
    const int akoff = (lane >> 4) << 3;
    const int brow = ((lane >> 4) << 3) + (lane & 7);
    const int bkoff = ((lane >> 3) & 1) << 3;

    float acc[4][4][4];
#pragma unroll
    for (int mf = 0; mf < 4; mf++)
#pragma unroll
        for (int nf = 0; nf < 4; nf++)
#pragma unroll
            for (int i = 0; i < 4; i++) acc[mf][nf][i] = 0.f;

    const int nch = K / KC;

    mm_load_tile(sm + 0 * TILEE, Ah, rowC, K, 0, tid);
    mm_load_tile(sm + 1 * TILEE, Al, rowC, K, 0, tid);
    mm_load_tile(sm + 2 * TILEE, Bh, colC, K, 0, tid);
    mm_load_tile(sm + 3 * TILEE, Bl, colC, K, 0, tid);
    CP_COMMIT();

    for (int ch = 0; ch < nch; ch++) {
        const int cur = ch & 1;
        const int nxt = cur ^ 1;
        if (ch + 1 < nch) {
            const int k0 = (ch + 1) * KC;
            mm_load_tile(sm + (nxt * 4 + 0) * TILEE, Ah, rowC, K, k0, tid);
            mm_load_tile(sm + (nxt * 4 + 1) * TILEE, Al, rowC, K, k0, tid);
            mm_load_tile(sm + (nxt * 4 + 2) * TILEE, Bh, colC, K, k0, tid);
            mm_load_tile(sm + (nxt * 4 + 3) * TILEE, Bl, colC, K, k0, tid);
        }
        CP_COMMIT();
        CP_WAIT(1);
        __syncthreads();

        const uint32_t aHb = sbase + (cur * 4 + 0) * (TILEE * 2);
        const uint32_t aLb = sbase + (cur * 4 + 1) * (TILEE * 2);
        const uint32_t bHb = sbase + (cur * 4 + 2) * (TILEE * 2);
        const uint32_t bLb = sbase + (cur * 4 + 3) * (TILEE * 2);

#pragma unroll
        for (int ks = 0; ks < 2; ks++) {
            const int k0 = ks * 16;
            uint32_t ah[4][4], al[4][4], bh[4][2], bl[4][2];
#pragma unroll
            for (int mf = 0; mf < 4; mf++) {
                uint32_t off = ((m0w + mf * 16 + arow) * AST + k0 + akoff) * 2;
                ldsm4(aHb + off, ah[mf]);
                ldsm4(aLb + off, al[mf]);
            }
#pragma unroll
            for (int nb = 0; nb < 2; nb++) {
                uint32_t off = ((n0w + nb * 16 + brow) * AST + k0 + bkoff) * 2;
                uint32_t r[4];
                ldsm4(bHb + off, r);
                bh[nb * 2][0] = r[0]; bh[nb * 2][1] = r[1];
                bh[nb * 2 + 1][0] = r[2]; bh[nb * 2 + 1][1] = r[3];
                ldsm4(bLb + off, r);
                bl[nb * 2][0] = r[0]; bl[nb * 2][1] = r[1];
                bl[nb * 2 + 1][0] = r[2]; bl[nb * 2 + 1][1] = r[3];
            }
#pragma unroll
            for (int mf = 0; mf < 4; mf++)
#pragma unroll
                for (int nf = 0; nf < 4; nf++) {
                    mma16816(acc[mf][nf], ah[mf], bh[nf]);
                    mma16816(acc[mf][nf], ah[mf], bl[nf]);
                    mma16816(acc[mf][nf], al[mf], bh[nf]);
                }
        }
        __syncthreads();
    }

    const int er = lane >> 2;
    const int ec = (lane & 3) * 2;
#pragma unroll
    for (int mf = 0; mf < 4; mf++)
#pragma unroll
        for (int nf = 0; nf < 4; nf++) {
            int row = rowC + m0w + mf * 16 + er;
            int col = colC + n0w + nf * 8 + ec;
            *(float2*)(C + (size_t)row * N + col) =
                make_float2(acc[mf][nf][0], acc[mf][nf][1]);
            *(float2*)(C + (size_t)(row + 8) * N + col) =
                make_float2(acc[mf][nf][2], acc[mf][nf][3]);
        }
}

// ---------------------------------------------------------------------------
// Weight transpose + bf16 hi/lo split: in [K,N] fp32 -> out [N,K] bf16 x2
// ---------------------------------------------------------------------------
__global__ void tr_split_kernel(const float* __restrict__ in,
                                __nv_bfloat16* __restrict__ oh,
                                __nv_bfloat16* __restrict__ ol,
                                int K, int N)
{
    __shared__ float t[32][33];
    int n0 = blockIdx.x * 32, k0 = blockIdx.y * 32;
    int tx = threadIdx.x, ty = threadIdx.y;
#pragma unroll
    for (int i = 0; i < 32; i += 8)
        t[ty + i][tx] = in[(size_t)(k0 + ty + i) * N + n0 + tx];
    __syncthreads();
#pragma unroll
    for (int i = 0; i < 32; i += 8) {
        float v = t[tx][ty + i];
        __nv_bfloat16 h = __float2bfloat16(v);
        float r = v - __bfloat162float(h);
        size_t o = (size_t)(n0 + ty + i) * K + k0 + tx;
        oh[o] = h;
        ol[o] = __float2bfloat16(r);
    }
}

__global__ void split_kernel(const float* __restrict__ in,
                             __nv_bfloat16* __restrict__ oh,
                             __nv_bfloat16* __restrict__ ol, int n)
{
    int i = blockIdx.x * blockDim.x + threadIdx.x;
    if (i >= n) return;
    float v = in[i];
    __nv_bfloat16 h = __float2bfloat16(v);
    oh[i] = h;
    ol[i] = __float2bfloat16(v - __bfloat162float(h));
}

// ---------------------------------------------------------------------------
// Small SGEMM (N=16/32): 128x64 tile, BK=16, 256 threads (fp32).
// ---------------------------------------------------------------------------
#define BM 128
#define BN 64
#define BK 16

__global__ void __launch_bounds__(256) sgemm_kernel(
    const float* __restrict__ A, const float* __restrict__ B,
    float* __restrict__ C, int M, int N, int K)
{
    __shared__ float As[BK][BM + 4];
    __shared__ float Bs[BK][BN];

    const int tid = threadIdx.x;
    const int tx = tid & 15;
    const int ty = tid >> 4;
    const int rowC = blockIdx.y * BM;
    const int colC = blockIdx.x * BN;

    const int rowA = tid >> 2;
    const int kA   = (tid & 3) * 4;
    const int rowB = tid >> 4;
    const int colB = (tid & 15) * 4;

    ull acc2[4][4];
#pragma unroll
    for (int r = 0; r < 4; r++)
#pragma unroll
        for (int jj = 0; jj < 4; jj++) acc2[r][jj] = 0ull;

    for (int k0 = 0; k0 < K; k0 += BK) {
#pragma unroll
        for (int r = 0; r < 2; r++) {
            int row = rowA + r * 64;
            float4 a = *(const float4*)(A + (size_t)(rowC + row) * K + k0 + kA);
            As[kA + 0][row] = a.x; As[kA + 1][row] = a.y;
            As[kA + 2][row] = a.z; As[kA + 3][row] = a.w;
        }
        {
            float4 bv = make_float4(0.f, 0.f, 0.f, 0.f);
            if (colC + colB < N)
                bv = *(const float4*)(B + (size_t)(k0 + rowB) * N + colC + colB);
            Bs[rowB][colB + 0] = bv.x; Bs[rowB][colB + 1] = bv.y;
            Bs[rowB][colB + 2] = bv.z; Bs[rowB][colB + 3] = bv.w;
        }
        __syncthreads();

#pragma unroll
        for (int kk = 0; kk < BK; kk++) {
            float4 b0 = *(const float4*)&Bs[kk][tx * 4];
            ull b2[4];
            b2[0] = pk2(b0.x, b0.x); b2[1] = pk2(b0.y, b0.y);
            b2[2] = pk2(b0.z, b0.z); b2[3] = pk2(b0.w, b0.w);
            ull a2[4];
#pragma unroll
            for (int r = 0; r < 4; r++)
                a2[r] = *(const ull*)&As[kk][ty * 8 + 2 * r];
#pragma unroll
            for (int r = 0; r < 4; r++)
#pragma unroll
                for (int jj = 0; jj < 4; jj++)
                    fma2(acc2[r][jj], a2[r], b2[jj]);
        }
        __syncthreads();
    }

    if (colC + tx * 4 < N) {
#pragma unroll
        for (int r = 0; r < 4; r++) {
            float lo[4], hi[4];
#pragma unroll
            for (int jj = 0; jj < 4; jj++) up2(acc2[r][jj], lo[jj], hi[jj]);
            int row0 = rowC + ty * 8 + 2 * r;
            *(float4*)(C + (size_t)row0 * N + colC + tx * 4) =
                make_float4(lo[0], lo[1], lo[2], lo[3]);
            *(float4*)(C + (size_t)(row0 + 1) * N + colC + tx * 4) =
                make_float4(hi[0], hi[1], hi[2], hi[3]);
        }
    }
}

// ---------------------------------------------------------------------------
// l2norm rows of 64 (q: scale by HD^-0.5; k: no scale). One warp per row.
// ---------------------------------------------------------------------------
__global__ void prep_norm_kernel()
{
    const int TQ = T_ * H_;
    const int TK = STEPS * H_;
    int w = (blockIdx.x * blockDim.x + threadIdx.x) >> 5;
    int lane = threadIdx.x & 31;
    if (w >= TQ + TK) return;
    float* p;
    float scl;
    if (w < TQ) { p = g_qbuf + (size_t)w * 64; scl = 0.125f; }
    else        { p = g_kbuf + (size_t)(w - TQ) * 64; scl = 1.0f; }
    float x0 = p[lane], x1 = p[lane + 32];
    float ss = x0 * x0 + x1 * x1;
#pragma unroll
    for (int o = 16; o; o >>= 1) ss += __shfl_xor_sync(0xffffffffu, ss, o);
    float rs = rsqrtf(ss + 1e-6f) * scl;
    p[lane] = x0 * rs;
    p[lane + 32] = x1 * rs;
}

// ---------------------------------------------------------------------------
// beta/dec precompute, written TRANSPOSED [h][s].
// ---------------------------------------------------------------------------
__global__ void prep_scalar_kernel(const float* __restrict__ A_log,
                                   const float* __restrict__ dt_bias)
{
    int i = blockIdx.x * blockDim.x + threadIdx.x;
    if (i >= STEPS * H_) return;
    int h = i & 15;
    int nh = (i >> 4) & 1;
    int t = i >> 5;
    int s = t * 2 + nh;
    float br = g_bbuf[i];
    g_betab[h * SPAD + s] = 2.0f / (1.0f + expf(-br));
    float d = 1.0f;
    if (nh == 0) {
        float a = g_abuf[t * H_ + h] + dt_bias[h];
        float sp = (a > 20.0f) ? a : log1pf(expf(a));
        d = expf(-expf(A_log[h]) * sp);
    }
    g_decb[h * SPAD + s] = d;
}

// ---------------------------------------------------------------------------
// Scan v3: 64 blocks (4 per head, 16 v-cols each) x 128 threads.
// 8 threads/column x 8 state rows (4 ull). 3 shfl hops per reduction.
// cp.async ring: 8 slots x 8 steps, lookahead 7. Fused 2-step math.
// ---------------------------------------------------------------------------
__device__ __forceinline__ void scan_prefetch(
    int gi, int tid,
    const float* kg, const float* qg, const float* vg,
    const float* bg, const float* dg,
    float (*sk)[GSTEPS*64], float (*sq)[(GSTEPS/2)*64],
    float (*sv)[GSTEPS*16], float (*sb)[16])
{
    int slot = gi & (NSLOT - 1);
    int s0 = gi * GSTEPS; if (s0 > STEPS) s0 = STEPS;
    int t0 = s0 >> 1;
    {   // k: 128 chunks -> all threads
        int si = tid >> 4, off = (tid & 15) * 4;
        cpasync16(&sk[slot][si * 64 + off], kg + (size_t)(s0 + si) * ROW + off);
    }
    if (tid < 64) {   // q: 64 chunks
        int ti = tid >> 4, off = (tid & 15) * 4;
        cpasync16(&sq[slot][ti * 64 + off], qg + (size_t)(t0 + ti) * ROW + off);
    } else if (tid < 96) {   // v: 8 steps x 16 cols = 32 chunks
        int c = tid - 64; int si = c >> 2, off = (c & 3) * 4;
        cpasync16(&sv[slot][si * 16 + off], vg + (size_t)(s0 + si) * ROW + off);
    }
    if (tid < 2)      cpasync16(&sb[slot][tid * 4], bg + s0 + tid * 4);
    else if (tid < 4) cpasync16(&sb[slot][8 + (tid - 2) * 4], dg + s0 + (tid - 2) * 4);
}

__device__ __forceinline__ void lds4u(const float* p, ull* u)
{
    const ull* up = (const ull*)p;
#pragma unroll
    for (int i = 0; i < 4; i++) u[i] = up[i];
}

__global__ void __launch_bounds__(128) scan_kernel()
{
    __shared__ float sk[NSLOT][GSTEPS*64];
    __shared__ float sq[NSLOT][(GSTEPS/2)*64];
    __shared__ float sv[NSLOT][GSTEPS*16];
    __shared__ float sb[NSLOT][16];

    const int h = blockIdx.x >> 2;
    const int quar = blockIdx.x & 3;
    const int tid = threadIdx.x;
    const int vloc = tid >> 3;            // 0..15
    const int j = tid & 7;                // 0..7 (row group)
    const int v = quar * 16 + vloc;

    const float* kg = g_kbuf + h * 64;
    const float* qg = g_qbuf + h * 64;
    const float* vg = g_vbuf + h * 64 + quar * 16;
    const float* bg = g_betab + h * SPAD;
    const float* dg = g_decb + h * SPAD;
    float* op = g_obuf + h * 64 + v;

    ull S2[4];
#pragma unroll
    for (int m = 0; m < 4; m++) S2[m] = 0ull;

#pragma unroll
    for (int pg = 0; pg < LOOKA; pg++) {
        scan_prefetch(pg, tid, kg, qg, vg, bg, dg, sk, sq, sv, sb);
        CP_COMMIT();
    }
    CP_WAIT(LOOKA - 1);
    __syncthreads();

    for (int g = 0; g < NGRP8; g++) {
        scan_prefetch(g + LOOKA, tid, kg, qg, vg, bg, dg, sk, sq, sv, sb);
        CP_COMMIT();

        const int slot = g & (NSLOT - 1);

#pragma unroll
        for (int it = 0; it < 4; it++) {
            ull ka2[4], kb2[4], qc2[4];
            lds4u(&sk[slot][(2 * it) * 64 + j * 8], ka2);
            lds4u(&sk[slot][(2 * it + 1) * 64 + j * 8], kb2);
            lds4u(&sq[slot][it * 64 + j * 8], qc2);

            float va = sv[slot][(2 * it) * 16 + vloc];
            float vb = sv[slot][(2 * it + 1) * 16 + vloc];
            float ba = sb[slot][2 * it];
            float bb = sb[slot][2 * it + 1];
            float da = sb[slot][8 + 2 * it];

            // three dots vs same S: pA=ka.S, pB=kb.S, pK=ka.kb (2-way split)
            ull a0 = 0ull, a1 = 0ull, b0 = 0ull, b1 = 0ull, c0 = 0ull, c1 = 0ull;
#pragma unroll
            for (int m = 0; m < 2; m++) {
                fma2(a0, ka2[m],     S2[m]);
                fma2(a1, ka2[m + 2], S2[m + 2]);
                fma2(b0, kb2[m],     S2[m]);
                fma2(b1, kb2[m + 2], S2[m + 2]);
                fma2(c0, ka2[m],     kb2[m]);
                fma2(c1, ka2[m + 2], kb2[m + 2]);
            }
            add2(a0, a0, a1); add2(b0, b0, b1); add2(c0, c0, c1);
            float lo, hi;
            up2(a0, lo, hi); float pA = lo + hi;
            up2(b0, lo, hi); float pB = lo + hi;
            up2(c0, lo, hi); float pK = lo + hi;
#pragma unroll
            for (int o = 1; o <= 4; o <<= 1) {
                pA += __shfl_xor_sync(0xffffffffu, pA, o);
                pB += __shfl_xor_sync(0xffffffffu, pB, o);
                pK += __shfl_xor_sync(0xffffffffu, pK, o);
            }

            float dva = (va - da * pA) * ba;
            float predb = fmaf(pK, dva, da * pB);
            float dvb = (vb - predb) * bb;

            ull da2  = pk2(da, da);
            ull dva2 = pk2(dva, dva);
            ull dvb2 = pk2(dvb, dvb);
#pragma unroll
            for (int m = 0; m < 4; m++) {
                ull t = mul2(ka2[m], dva2);
                fma2(t, kb2[m], dvb2);
                fma2(t, S2[m], da2);
                S2[m] = t;
            }

            ull o0 = 0ull, o1 = 0ull;
#pragma unroll
            for (int m = 0; m < 2; m++) {
                fma2(o0, qc2[m],     S2[m]);
                fma2(o1, qc2[m + 2], S2[m + 2]);
            }
            add2(o0, o0, o1);
            up2(o0, lo, hi);
            float o = lo + hi;
#pragma unroll
            for (int s = 1; s <= 4; s <<= 1)
                o += __shfl_xor_sync(0xffffffffu, o, s);
            if (j == 0) op[(size_t)(g * 4 + it) * ROW] = o;
        }

        CP_WAIT(LOOKA - 1);
        __syncthreads();
    }
}

// ---------------------------------------------------------------------------
// Gated RMSNorm + swish gate, in-place on g_obuf. One warp per (t,h) row.
// ---------------------------------------------------------------------------
__global__ void post_kernel(const float* __restrict__ nw)
{
    int w = (blockIdx.x * blockDim.x + threadIdx.x) >> 5;
    int lane = threadIdx.x & 31;
    if (w >= T_ * H_) return;
    float* p = g_obuf + (size_t)w * 64;
    const float* gp = g_gbuf + (size_t)w * 64;
    float x0 = p[lane], x1 = p[lane + 32];
    float ss = x0 * x0 + x1 * x1;
#pragma unroll
    for (int o = 16; o; o >>= 1) ss += __shfl_xor_sync(0xffffffffu, ss, o);
    float rs = rsqrtf(ss * (1.0f / 64.0f) + 1e-5f);
    float g0 = gp[lane], g1 = gp[lane + 32];
    float w0 = nw[lane], w1 = nw[lane + 32];
    float sg0 = g0 / (1.0f + expf(-g0));
    float sg1 = g1 / (1.0f + expf(-g1));
    p[lane]      = x0 * rs * w0 * sg0;
    p[lane + 32] = x1 * rs * w1 * sg1;
}

// ---------------------------------------------------------------------------
// Host launcher. Capture-legal fork: s1's FIRST op waits on evRoot recorded
// on the capture-origin stream s0 before any side-stream launch.
// ---------------------------------------------------------------------------
extern "C" void kernel_launch(void* const* d_in, const int* in_sizes, int n_in,
                              void* d_out, int out_size)
{
    const float* x       = (const float*)d_in[0];
    const float* Wq      = (const float*)d_in[1];
    const float* Wk      = (const float*)d_in[2];
    const float* Wv      = (const float*)d_in[3];
    const float* Wb      = (const float*)d_in[4];
    const float* Wa      = (const float*)d_in[5];
    const float* A_log   = (const float*)d_in[6];
    const float* dt_bias = (const float*)d_in[7];
    const float* Wg      = (const float*)d_in[8];
    const float* nw      = (const float*)d_in[9];
    const float* Wo      = (const float*)d_in[10];
    float* out = (float*)d_out;

    cudaFuncSetAttribute(mm_wmma_kernel,
        cudaFuncAttributeMaxDynamicSharedMemorySize, MM_SMEM);

    static cudaStream_t s1 = nullptr;
    static cudaEvent_t evRoot = nullptr, evX = nullptr, evPre = nullptr,
                       evG = nullptr, evB = nullptr;
    if (!s1) {
        cudaStreamCreateWithFlags(&s1, cudaStreamNonBlocking);
        cudaEventCreateWithFlags(&evRoot, cudaEventDisableTiming);
        cudaEventCreateWithFlags(&evX, cudaEventDisableTiming);
        cudaEventCreateWithFlags(&evPre, cudaEventDisableTiming);
        cudaEventCreateWithFlags(&evG, cudaEventDisableTiming);
        cudaEventCreateWithFlags(&evB, cudaEventDisableTiming);
    }
    cudaStream_t s0 = 0;

    float *qb, *kb, *vb, *gb, *bb, *ab, *ob;
    cudaGetSymbolAddress((void**)&qb, g_qbuf);
    cudaGetSymbolAddress((void**)&kb, g_kbuf);
    cudaGetSymbolAddress((void**)&vb, g_vbuf);
    cudaGetSymbolAddress((void**)&gb, g_gbuf);
    cudaGetSymbolAddress((void**)&bb, g_bbuf);
    cudaGetSymbolAddress((void**)&ab, g_abuf);
    cudaGetSymbolAddress((void**)&ob, g_obuf);

    __nv_bfloat16 *xh, *xl, *oh, *ol;
    __nv_bfloat16 *wqh, *wql, *wkh, *wkl, *wvh, *wvl, *wgh, *wgl, *woh, *wol;
    cudaGetSymbolAddress((void**)&xh, g_xh);   cudaGetSymbolAddress((void**)&xl, g_xl);
    cudaGetSymbolAddress((void**)&oh, g_oh);   cudaGetSymbolAddress((void**)&ol, g_ol);
    cudaGetSymbolAddress((void**)&wqh, g_wqh); cudaGetSymbolAddress((void**)&wql, g_wql);
    cudaGetSymbolAddress((void**)&wkh, g_wkh); cudaGetSymbolAddress((void**)&wkl, g_wkl);
    cudaGetSymbolAddress((void**)&wvh, g_wvh); cudaGetSymbolAddress((void**)&wvl, g_wvl);
    cudaGetSymbolAddress((void**)&wgh, g_wgh); cudaGetSymbolAddress((void**)&wgl, g_wgl);
    cudaGetSymbolAddress((void**)&woh, g_woh); cudaGetSymbolAddress((void**)&wol, g_wol);

    dim3 trb(32, 8);

    // capture-legal fork point
    cudaEventRecord(evRoot, s0);
    cudaStreamWaitEvent(s1, evRoot, 0);

    // side stream: Wb/Wa projections + scalar prep (need only x)
    sgemm_kernel<<<dim3(1, T_ / BM), 256, 0, s1>>>(x, Wb, bb, T_, 32, D_);
    sgemm_kernel<<<dim3(1, T_ / BM), 256, 0, s1>>>(x, Wa, ab, T_, 16, D_);
    prep_scalar_kernel<<<(STEPS * H_) / 256, 256, 0, s1>>>(A_log, dt_bias);
    cudaEventRecord(evB, s1);

    // main stream: x split + k/v/q pipelines
    split_kernel<<<(T_ * D_) / 256, 256, 0, s0>>>(x, xh, xl, T_ * D_);
    cudaEventRecord(evX, s0);
    tr_split_kernel<<<dim3(2048/32, 1024/32), trb, 0, s0>>>(Wk, wkh, wkl, D_, 2048);
    tr_split_kernel<<<dim3(2048/32, 1024/32), trb, 0, s0>>>(Wv, wvh, wvl, D_, 2048);
    tr_split_kernel<<<dim3(1024/32, 1024/32), trb, 0, s0>>>(Wq, wqh, wql, D_, 1024);
    mm_wmma_kernel<<<dim3(2048/128, T_/128), 256, MM_SMEM, s0>>>(xh, xl, wkh, wkl, kb, T_, 2048, D_);
    mm_wmma_kernel<<<dim3(2048/128, T_/128), 256, MM_SMEM, s0>>>(xh, xl, wvh, wvl, vb, T_, 2048, D_);
    mm_wmma_kernel<<<dim3(1024/128, T_/128), 256, MM_SMEM, s0>>>(xh, xl, wqh, wql, qb, T_, 1024, D_);

    {
        int warps = T_ * H_ + STEPS * H_;
        prep_norm_kernel<<<(warps + 7) / 8, 256, 0, s0>>>();
    }
    cudaEventRecord(evPre, s0);

    // scan (64 SMs) on main stream; needs beta/dec from side stream
    cudaStreamWaitEvent(s0, evB, 0);
    scan_kernel<<<64, 128, 0, s0>>>();

    // side stream: gate pipeline + Wo prep run UNDER the scan on idle SMs
    cudaStreamWaitEvent(s1, evX, 0);
    cudaStreamWaitEvent(s1, evPre, 0);
    tr_split_kernel<<<dim3(1024/32, 1024/32), trb, 0, s1>>>(Wg, wgh, wgl, D_, 1024);
    mm_wmma_kernel<<<dim3(1024/128, T_/128), 256, MM_SMEM, s1>>>(xh, xl, wgh, wgl, gb, T_, 1024, D_);
    tr_split_kernel<<<dim3(1024/32, 1024/32), trb, 0, s1>>>(Wo, woh, wol, ROW, 1024);
    cudaEventRecord(evG, s1);

    // join, then post + output projection
    cudaStreamWaitEvent(s0, evG, 0);
    post_kernel<<<(T_ * H_ + 7) / 8, 256, 0, s0>>>(nw);
    split_kernel<<<(T_ * ROW) / 256, 256, 0, s0>>>(ob, oh, ol, T_ * ROW);
    mm_wmma_kernel<<<dim3(1024/128, T_/128), 256, MM_SMEM, s0>>>(oh, ol, woh, wol, out, T_, 1024, ROW);
}

// round 17
// speedup vs baseline: 1.8426x; 1.8426x over previous
#include <cuda_runtime.h>
#include <cuda_bf16.h>
#include <math.h>
#include <stdint.h>

// ---------------------------------------------------------------------------
// Problem dims (fixed)
// ---------------------------------------------------------------------------
#define T_   2048
#define D_   1024
#define H_   16
#define HD_  64
#define NH_  2
#define STEPS (T_*NH_)          // 4096
#define ROW  (H_*HD_)           // 1024
#define SPAD (STEPS + 8)
#define GSTEPS 8
#define NSLOT 8
#define LOOKA 7
#define NGRP8 (STEPS/GSTEPS)

// ---------------------------------------------------------------------------
// Scratch (static device memory; allocation-free).
// ---------------------------------------------------------------------------
__device__ __align__(256) float g_qbuf[(T_ + 4) * ROW];
__device__ __align__(256) float g_kbuf[SPAD * ROW];
__device__ __align__(256) float g_vbuf[SPAD * ROW];
__device__ __align__(256) float g_gbuf[T_ * ROW];
__device__ __align__(256) float g_bbuf[T_ * (NH_ * H_)];
__device__ __align__(256) float g_abuf[T_ * H_];
__device__ __align__(256) float g_betab[H_ * SPAD];
__device__ __align__(256) float g_decb[H_ * SPAD];
__device__ __align__(256) float g_obuf[T_ * ROW];

// bf16 split buffers (hi/lo), weights transposed to [N][K]
__device__ __align__(256) __nv_bfloat16 g_xh[T_ * D_],    g_xl[T_ * D_];
__device__ __align__(256) __nv_bfloat16 g_oh[T_ * ROW],   g_ol[T_ * ROW];
__device__ __align__(256) __nv_bfloat16 g_wqh[1024 * D_], g_wql[1024 * D_];
__device__ __align__(256) __nv_bfloat16 g_wkh[2048 * D_], g_wkl[2048 * D_];
__device__ __align__(256) __nv_bfloat16 g_wvh[2048 * D_], g_wvl[2048 * D_];
__device__ __align__(256) __nv_bfloat16 g_wgh[1024 * D_], g_wgl[1024 * D_];
__device__ __align__(256) __nv_bfloat16 g_woh[1024 * ROW], g_wol[1024 * ROW];

// ---------------------------------------------------------------------------
// f32x2 packed helpers
// ---------------------------------------------------------------------------
typedef unsigned long long ull;

__device__ __forceinline__ void fma2(ull& d, ull a, ull b) {
    asm("fma.rn.f32x2 %0, %1, %2, %3;" : "=l"(d) : "l"(a), "l"(b), "l"(d));
}
__device__ __forceinline__ void add2(ull& d, ull a, ull b) {
    asm("add.rn.f32x2 %0, %1, %2;" : "=l"(d) : "l"(a), "l"(b));
}
__device__ __forceinline__ ull mul2(ull a, ull b) {
    ull d;
    asm("mul.rn.f32x2 %0, %1, %2;" : "=l"(d) : "l"(a), "l"(b));
    return d;
}
__device__ __forceinline__ ull pk2(float x, float y) {
    ull r;
    asm("mov.b64 %0, {%1, %2};" : "=l"(r)
        : "r"(__float_as_uint(x)), "r"(__float_as_uint(y)));
    return r;
}
__device__ __forceinline__ void up2(ull v, float& lo, float& hi) {
    unsigned a, b;
    asm("mov.b64 {%0, %1}, %2;" : "=r"(a), "=r"(b) : "l"(v));
    lo = __uint_as_float(a); hi = __uint_as_float(b);
}

// ---------------------------------------------------------------------------
// cp.async helpers (16 BYTES per op)
// ---------------------------------------------------------------------------
__device__ __forceinline__ void cpasync16(void* dst, const void* src) {
    unsigned d = (unsigned)__cvta_generic_to_shared(dst);
    asm volatile("cp.async.cg.shared.global [%0], [%1], 16;" :: "r"(d), "l"(src));
}
#define CP_COMMIT() asm volatile("cp.async.commit_group;")
#define CP_WAIT(n)  asm volatile("cp.async.wait_group %0;" :: "n"(n))

__device__ __forceinline__ uint32_t smem_u32(const void* p) {
    uint32_t a;
    asm("{ .reg .u64 t; cvta.to.shared.u64 t, %1; cvt.u32.u64 %0, t; }"
        : "=r"(a) : "l"(p));
    return a;
}

// ---------------------------------------------------------------------------
// warp-MMA primitives
// ---------------------------------------------------------------------------
__device__ __forceinline__ void ldsm4(uint32_t addr, uint32_t* r) {
    asm volatile("ldmatrix.sync.aligned.m8n8.x4.shared.b16 {%0,%1,%2,%3}, [%4];"
        : "=r"(r[0]), "=r"(r[1]), "=r"(r[2]), "=r"(r[3]) : "r"(addr));
}
__device__ __forceinline__ void mma16816(float* d, const uint32_t* a, const uint32_t* b) {
    asm volatile(
        "mma.sync.aligned.m16n8k16.row.col.f32.bf16.bf16.f32 "
        "{%0,%1,%2,%3}, {%4,%5,%6,%7}, {%8,%9}, {%0,%1,%2,%3};"
        : "+f"(d[0]), "+f"(d[1]), "+f"(d[2]), "+f"(d[3])
        : "r"(a[0]), "r"(a[1]), "r"(a[2]), "r"(a[3]), "r"(b[0]), "r"(b[1]));
}

// ---------------------------------------------------------------------------
// Warp-MMA GEMM (R8-proven, unchanged): 128x128 CTA tile, 256 threads.
// ---------------------------------------------------------------------------
#define KC    32
#define AST   40
#define TILEE (128 * AST)
#define MM_SMEM (2 * 4 * TILEE * 2)   // 81920 B

__device__ __forceinline__ void mm_load_tile(
    __nv_bfloat16* dst, const __nv_bfloat16* src, int row0, int K, int k0, int tid)
{
#pragma unroll
    for (int i = 0; i < 2; i++) {
        int c0 = tid + i * 256;
        int r = c0 >> 2, c = c0 & 3;
        cpasync16(dst + r * AST + c * 8, src + (size_t)(row0 + r) * K + k0 + c * 8);
    }
}

__global__ void __launch_bounds__(256) mm_wmma_kernel(
    const __nv_bfloat16* __restrict__ Ah, const __nv_bfloat16* __restrict__ Al,
    const __nv_bfloat16* __restrict__ Bh, const __nv_bfloat16* __restrict__ Bl,
    float* __restrict__ C, int M, int N, int K)
{
    extern __shared__ __nv_bfloat16 sm[];
    const uint32_t sbase = smem_u32(sm);
    const int tid = threadIdx.x;
    const int wid = tid >> 5;
    const int lane = tid & 31;
    const int rowC = blockIdx.y * 128;
    const int colC = blockIdx.x * 128;
    const int wr = wid >> 2;
    const int wc = wid & 3;
    const int m0w = wr * 64;
    const int n0w = wc * 32;

    const int arow = lane & 15;
    const int akoff = (lane >> 4) << 3;
    const int brow = ((lane >> 4) << 3) + (lane & 7);
    const int bkoff = ((lane >> 3) & 1) << 3;

    float acc[4][4][4];
#pragma unroll
    for (int mf = 0; mf < 4; mf++)
#pragma unroll
        for (int nf = 0; nf < 4; nf++)
#pragma unroll
            for (int i = 0; i < 4; i++) acc[mf][nf][i] = 0.f;

    const int nch = K / KC;

    mm_load_tile(sm + 0 * TILEE, Ah, rowC, K, 0, tid);
    mm_load_tile(sm + 1 * TILEE, Al, rowC, K, 0, tid);
    mm_load_tile(sm + 2 * TILEE, Bh, colC, K, 0, tid);
    mm_load_tile(sm + 3 * TILEE, Bl, colC, K, 0, tid);
    CP_COMMIT();

    for (int ch = 0; ch < nch; ch++) {
        const int cur = ch & 1;
        const int nxt = cur ^ 1;
        if (ch + 1 < nch) {
            const int k0 = (ch + 1) * KC;
            mm_load_tile(sm + (nxt * 4 + 0) * TILEE, Ah, rowC, K, k0, tid);
            mm_load_tile(sm + (nxt * 4 + 1) * TILEE, Al, rowC, K, k0, tid);
            mm_load_tile(sm + (nxt * 4 + 2) * TILEE, Bh, colC, K, k0, tid);
            mm_load_tile(sm + (nxt * 4 + 3) * TILEE, Bl, colC, K, k0, tid);
        }
        CP_COMMIT();
        CP_WAIT(1);
        __syncthreads();

        const uint32_t aHb = sbase + (cur * 4 + 0) * (TILEE * 2);
        const uint32_t aLb = sbase + (cur * 4 + 1) * (TILEE * 2);
        const uint32_t bHb = sbase + (cur * 4 + 2) * (TILEE * 2);
        const uint32_t bLb = sbase + (cur * 4 + 3) * (TILEE * 2);

#pragma unroll
        for (int ks = 0; ks < 2; ks++) {
            const int k0 = ks * 16;
            uint32_t ah[4][4], al[4][4], bh[4][2], bl[4][2];
#pragma unroll
            for (int mf = 0; mf < 4; mf++) {
                uint32_t off = ((m0w + mf * 16 + arow) * AST + k0 + akoff) * 2;
                ldsm4(aHb + off, ah[mf]);
                ldsm4(aLb + off, al[mf]);
            }
#pragma unroll
            for (int nb = 0; nb < 2; nb++) {
                uint32_t off = ((n0w + nb * 16 + brow) * AST + k0 + bkoff) * 2;
                uint32_t r[4];
                ldsm4(bHb + off, r);
                bh[nb * 2][0] = r[0]; bh[nb * 2][1] = r[1];
                bh[nb * 2 + 1][0] = r[2]; bh[nb * 2 + 1][1] = r[3];
                ldsm4(bLb + off, r);
                bl[nb * 2][0] = r[0]; bl[nb * 2][1] = r[1];
                bl[nb * 2 + 1][0] = r[2]; bl[nb * 2 + 1][1] = r[3];
            }
#pragma unroll
            for (int mf = 0; mf < 4; mf++)
#pragma unroll
                for (int nf = 0; nf < 4; nf++) {
                    mma16816(acc[mf][nf], ah[mf], bh[nf]);
                    mma16816(acc[mf][nf], ah[mf], bl[nf]);
                    mma16816(acc[mf][nf], al[mf], bh[nf]);
                }
        }
        __syncthreads();
    }

    const int er = lane >> 2;
    const int ec = (lane & 3) * 2;
#pragma unroll
    for (int mf = 0; mf < 4; mf++)
#pragma unroll
        for (int nf = 0; nf < 4; nf++) {
            int row = rowC + m0w + mf * 16 + er;
            int col = colC + n0w + nf * 8 + ec;
            *(float2*)(C + (size_t)row * N + col) =
                make_float2(acc[mf][nf][0], acc[mf][nf][1]);
            *(float2*)(C + (size_t)(row + 8) * N + col) =
                make_float2(acc[mf][nf][2], acc[mf][nf][3]);
        }
}

// ---------------------------------------------------------------------------
// Weight transpose + bf16 hi/lo split: in [K,N] fp32 -> out [N,K] bf16 x2
// ---------------------------------------------------------------------------
__global__ void tr_split_kernel(const float* __restrict__ in,
                                __nv_bfloat16* __restrict__ oh,
                                __nv_bfloat16* __restrict__ ol,
                                int K, int N)
{
    __shared__ float t[32][33];
    int n0 = blockIdx.x * 32, k0 = blockIdx.y * 32;
    int tx = threadIdx.x, ty = threadIdx.y;
#pragma unroll
    for (int i = 0; i < 32; i += 8)
        t[ty + i][tx] = in[(size_t)(k0 + ty + i) * N + n0 + tx];
    __syncthreads();
#pragma unroll
    for (int i = 0; i < 32; i += 8) {
        float v = t[tx][ty + i];
        __nv_bfloat16 h = __float2bfloat16(v);
        float r = v - __bfloat162float(h);
        size_t o = (size_t)(n0 + ty + i) * K + k0 + tx;
        oh[o] = h;
        ol[o] = __float2bfloat16(r);
    }
}

__global__ void split_kernel(const float* __restrict__ in,
                             __nv_bfloat16* __restrict__ oh,
                             __nv_bfloat16* __restrict__ ol, int n)
{
    int i = blockIdx.x * blockDim.x + threadIdx.x;
    if (i >= n) return;
    float v = in[i];
    __nv_bfloat16 h = __float2bfloat16(v);
    oh[i] = h;
    ol[i] = __float2bfloat16(v - __bfloat162float(h));
}

// ---------------------------------------------------------------------------
// Small SGEMM (N=16/32): 128x64 tile, BK=16, 256 threads (fp32).
// ---------------------------------------------------------------------------
#define BM 128
#define BN 64
#define BK 16

__global__ void __launch_bounds__(256) sgemm_kernel(
    const float* __restrict__ A, const float* __restrict__ B,
    float* __restrict__ C, int M, int N, int K)
{
    __shared__ float As[BK][BM + 4];
    __shared__ float Bs[BK][BN];

    const int tid = threadIdx.x;
    const int tx = tid & 15;
    const int ty = tid >> 4;
    const int rowC = blockIdx.y * BM;
    const int colC = blockIdx.x * BN;

    const int rowA = tid >> 2;
    const int kA   = (tid & 3) * 4;
    const int rowB = tid >> 4;
    const int colB = (tid & 15) * 4;

    ull acc2[4][4];
#pragma unroll
    for (int r = 0; r < 4; r++)
#pragma unroll
        for (int jj = 0; jj < 4; jj++) acc2[r][jj] = 0ull;

    for (int k0 = 0; k0 < K; k0 += BK) {
#pragma unroll
        for (int r = 0; r < 2; r++) {
            int row = rowA + r * 64;
            float4 a = *(const float4*)(A + (size_t)(rowC + row) * K + k0 + kA);
            As[kA + 0][row] = a.x; As[kA + 1][row] = a.y;
            As[kA + 2][row] = a.z; As[kA + 3][row] = a.w;
        }
        {
            float4 bv = make_float4(0.f, 0.f, 0.f, 0.f);
            if (colC + colB < N)
                bv = *(const float4*)(B + (size_t)(k0 + rowB) * N + colC + colB);
            Bs[rowB][colB + 0] = bv.x; Bs[rowB][colB + 1] = bv.y;
            Bs[rowB][colB + 2] = bv.z; Bs[rowB][colB + 3] = bv.w;
        }
        __syncthreads();

#pragma unroll
        for (int kk = 0; kk < BK; kk++) {
            float4 b0 = *(const float4*)&Bs[kk][tx * 4];
            ull b2[4];
            b2[0] = pk2(b0.x, b0.x); b2[1] = pk2(b0.y, b0.y);
            b2[2] = pk2(b0.z, b0.z); b2[3] = pk2(b0.w, b0.w);
            ull a2[4];
#pragma unroll
            for (int r = 0; r < 4; r++)
                a2[r] = *(const ull*)&As[kk][ty * 8 + 2 * r];
#pragma unroll
            for (int r = 0; r < 4; r++)
#pragma unroll
                for (int jj = 0; jj < 4; jj++)
                    fma2(acc2[r][jj], a2[r], b2[jj]);
        }
        __syncthreads();
    }

    if (colC + tx * 4 < N) {
#pragma unroll
        for (int r = 0; r < 4; r++) {
            float lo[4], hi[4];
#pragma unroll
            for (int jj = 0; jj < 4; jj++) up2(acc2[r][jj], lo[jj], hi[jj]);
            int row0 = rowC + ty * 8 + 2 * r;
            *(float4*)(C + (size_t)row0 * N + colC + tx * 4) =
                make_float4(lo[0], lo[1], lo[2], lo[3]);
            *(float4*)(C + (size_t)(row0 + 1) * N + colC + tx * 4) =
                make_float4(hi[0], hi[1], hi[2], hi[3]);
        }
    }
}

// ---------------------------------------------------------------------------
// l2norm rows of 64 (q: scale by HD^-0.5; k: no scale). One warp per row.
// ---------------------------------------------------------------------------
__global__ void prep_norm_kernel()
{
    const int TQ = T_ * H_;
    const int TK = STEPS * H_;
    int w = (blockIdx.x * blockDim.x + threadIdx.x) >> 5;
    int lane = threadIdx.x & 31;
    if (w >= TQ + TK) return;
    float* p;
    float scl;
    if (w < TQ) { p = g_qbuf + (size_t)w * 64; scl = 0.125f; }
    else        { p = g_kbuf + (size_t)(w - TQ) * 64; scl = 1.0f; }
    float x0 = p[lane], x1 = p[lane + 32];
    float ss = x0 * x0 + x1 * x1;
#pragma unroll
    for (int o = 16; o; o >>= 1) ss += __shfl_xor_sync(0xffffffffu, ss, o);
    float rs = rsqrtf(ss + 1e-6f) * scl;
    p[lane] = x0 * rs;
    p[lane + 32] = x1 * rs;
}

// ---------------------------------------------------------------------------
// beta/dec precompute, written TRANSPOSED [h][s].
// ---------------------------------------------------------------------------
__global__ void prep_scalar_kernel(const float* __restrict__ A_log,
                                   const float* __restrict__ dt_bias)
{
    int i = blockIdx.x * blockDim.x + threadIdx.x;
    if (i >= STEPS * H_) return;
    int h = i & 15;
    int nh = (i >> 4) & 1;
    int t = i >> 5;
    int s = t * 2 + nh;
    float br = g_bbuf[i];
    g_betab[h * SPAD + s] = 2.0f / (1.0f + expf(-br));
    float d = 1.0f;
    if (nh == 0) {
        float a = g_abuf[t * H_ + h] + dt_bias[h];
        float sp = (a > 20.0f) ? a : log1pf(expf(a));
        d = expf(-expf(A_log[h]) * sp);
    }
    g_decb[h * SPAD + s] = d;
}

// ---------------------------------------------------------------------------
// Scan (R14-proven): 32 blocks (2/head) x 128 threads, 4 thr/col x 16 rows,
// cp.async ring 8 slots x 8 steps, lookahead 7, fused 2-step math.
// ---------------------------------------------------------------------------
__device__ __forceinline__ void scan_prefetch(
    int gi, int tid,
    const float* kg, const float* qg, const float* vg,
    const float* bg, const float* dg,
    float (*sk)[GSTEPS*64], float (*sq)[(GSTEPS/2)*64],
    float (*sv)[GSTEPS*32], float (*sb)[16])
{
    int slot = gi & (NSLOT - 1);
    int s0 = gi * GSTEPS; if (s0 > STEPS) s0 = STEPS;
    int t0 = s0 >> 1;
    {
        int si = tid >> 4, off = (tid & 15) * 4;
        cpasync16(&sk[slot][si * 64 + off], kg + (size_t)(s0 + si) * ROW + off);
    }
    if (tid < 64) {
        int ti = tid >> 4, off = (tid & 15) * 4;
        cpasync16(&sq[slot][ti * 64 + off], qg + (size_t)(t0 + ti) * ROW + off);
    } else {
        int c = tid - 64; int si = c >> 3, off = (c & 7) * 4;
        cpasync16(&sv[slot][si * 32 + off], vg + (size_t)(s0 + si) * ROW + off);
    }
    if (tid < 2)      cpasync16(&sb[slot][tid * 4], bg + s0 + tid * 4);
    else if (tid < 4) cpasync16(&sb[slot][8 + (tid - 2) * 4], dg + s0 + (tid - 2) * 4);
}

__device__ __forceinline__ void lds8u(const float* p, ull* u)
{
    const ull* up = (const ull*)p;
#pragma unroll
    for (int i = 0; i < 8; i++) u[i] = up[i];
}

__global__ void __launch_bounds__(128) scan_kernel()
{
    __shared__ float sk[NSLOT][GSTEPS*64];
    __shared__ float sq[NSLOT][(GSTEPS/2)*64];
    __shared__ float sv[NSLOT][GSTEPS*32];
    __shared__ float sb[NSLOT][16];

    const int h = blockIdx.x >> 1;
    const int half = blockIdx.x & 1;
    const int tid = threadIdx.x;
    const int vloc = tid >> 2;
    const int j = tid & 3;
    const int v = (half << 5) + vloc;

    const float* kg = g_kbuf + h * 64;
    const float* qg = g_qbuf + h * 64;
    const float* vg = g_vbuf + h * 64 + half * 32;
    const float* bg = g_betab + h * SPAD;
    const float* dg = g_decb + h * SPAD;
    float* op = g_obuf + h * 64 + v;

    ull S2[8];
#pragma unroll
    for (int m = 0; m < 8; m++) S2[m] = 0ull;

#pragma unroll
    for (int pg = 0; pg < LOOKA; pg++) {
        scan_prefetch(pg, tid, kg, qg, vg, bg, dg, sk, sq, sv, sb);
        CP_COMMIT();
    }
    CP_WAIT(LOOKA - 1);
    __syncthreads();

    for (int g = 0; g < NGRP8; g++) {
        scan_prefetch(g + LOOKA, tid, kg, qg, vg, bg, dg, sk, sq, sv, sb);
        CP_COMMIT();

        const int slot = g & (NSLOT - 1);

#pragma unroll
        for (int it = 0; it < 4; it++) {
            ull ka2[8], kb2[8], qc2[8];
            lds8u(&sk[slot][(2 * it) * 64 + j * 16], ka2);
            lds8u(&sk[slot][(2 * it + 1) * 64 + j * 16], kb2);
            lds8u(&sq[slot][it * 64 + j * 16], qc2);

            float va = sv[slot][(2 * it) * 32 + vloc];
            float vb = sv[slot][(2 * it + 1) * 32 + vloc];
            float ba = sb[slot][2 * it];
            float bb = sb[slot][2 * it + 1];
            float da = sb[slot][8 + 2 * it];

            ull a0 = 0ull, a1 = 0ull, b0 = 0ull, b1 = 0ull, c0 = 0ull, c1 = 0ull;
#pragma unroll
            for (int m = 0; m < 4; m++) {
                fma2(a0, ka2[m],     S2[m]);
                fma2(a1, ka2[m + 4], S2[m + 4]);
                fma2(b0, kb2[m],     S2[m]);
                fma2(b1, kb2[m + 4], S2[m + 4]);
                fma2(c0, ka2[m],     kb2[m]);
                fma2(c1, ka2[m + 4], kb2[m + 4]);
            }
            add2(a0, a0, a1); add2(b0, b0, b1); add2(c0, c0, c1);
            float lo, hi;
            up2(a0, lo, hi); float pA = lo + hi;
            up2(b0, lo, hi); float pB = lo + hi;
            up2(c0, lo, hi); float pK = lo + hi;
            pA += __shfl_xor_sync(0xffffffffu, pA, 1);
            pB += __shfl_xor_sync(0xffffffffu, pB, 1);
            pK += __shfl_xor_sync(0xffffffffu, pK, 1);
            pA += __shfl_xor_sync(0xffffffffu, pA, 2);
            pB += __shfl_xor_sync(0xffffffffu, pB, 2);
            pK += __shfl_xor_sync(0xffffffffu, pK, 2);

            float dva = (va - da * pA) * ba;
            float predb = fmaf(pK, dva, da * pB);
            float dvb = (vb - predb) * bb;

            ull da2  = pk2(da, da);
            ull dva2 = pk2(dva, dva);
            ull dvb2 = pk2(dvb, dvb);
#pragma unroll
            for (int m = 0; m < 8; m++) {
                ull t = mul2(ka2[m], dva2);
                fma2(t, kb2[m], dvb2);
                fma2(t, S2[m], da2);
                S2[m] = t;
            }

            ull o0 = 0ull, o1 = 0ull;
#pragma unroll
            for (int m = 0; m < 4; m++) {
                fma2(o0, qc2[m],     S2[m]);
                fma2(o1, qc2[m + 4], S2[m + 4]);
            }
            add2(o0, o0, o1);
            up2(o0, lo, hi);
            float o = lo + hi;
            o += __shfl_xor_sync(0xffffffffu, o, 1);
            o += __shfl_xor_sync(0xffffffffu, o, 2);
            if (j == 0) op[(size_t)(g * 4 + it) * ROW] = o;
        }

        CP_WAIT(LOOKA - 1);
        __syncthreads();
    }
}

// ---------------------------------------------------------------------------
// Gated RMSNorm + swish gate; writes bf16 hi/lo split DIRECTLY (fused
// epilogue split — g_oh/g_ol are the out-GEMM inputs). One warp per row.
// ---------------------------------------------------------------------------
__global__ void post_kernel(const float* __restrict__ nw)
{
    int w = (blockIdx.x * blockDim.x + threadIdx.x) >> 5;
    int lane = threadIdx.x & 31;
    if (w >= T_ * H_) return;
    const float* p = g_obuf + (size_t)w * 64;
    const float* gp = g_gbuf + (size_t)w * 64;
    float x0 = p[lane], x1 = p[lane + 32];
    float ss = x0 * x0 + x1 * x1;
#pragma unroll
    for (int o = 16; o; o >>= 1) ss += __shfl_xor_sync(0xffffffffu, ss, o);
    float rs = rsqrtf(ss * (1.0f / 64.0f) + 1e-5f);
    float g0 = gp[lane], g1 = gp[lane + 32];
    float w0 = nw[lane], w1 = nw[lane + 32];
    float sg0 = g0 / (1.0f + expf(-g0));
    float sg1 = g1 / (1.0f + expf(-g1));
    float r0 = x0 * rs * w0 * sg0;
    float r1 = x1 * rs * w1 * sg1;
    size_t base = (size_t)w * 64;
    __nv_bfloat16 h0 = __float2bfloat16(r0);
    __nv_bfloat16 h1 = __float2bfloat16(r1);
    g_oh[base + lane]      = h0;
    g_oh[base + lane + 32] = h1;
    g_ol[base + lane]      = __float2bfloat16(r0 - __bfloat162float(h0));
    g_ol[base + lane + 32] = __float2bfloat16(r1 - __bfloat162float(h1));
}

// ---------------------------------------------------------------------------
// Host launcher (R14 schedule exactly; epilogue split fused into post).
// ---------------------------------------------------------------------------
extern "C" void kernel_launch(void* const* d_in, const int* in_sizes, int n_in,
                              void* d_out, int out_size)
{
    const float* x       = (const float*)d_in[0];
    const float* Wq      = (const float*)d_in[1];
    const float* Wk      = (const float*)d_in[2];
    const float* Wv      = (const float*)d_in[3];
    const float* Wb      = (const float*)d_in[4];
    const float* Wa      = (const float*)d_in[5];
    const float* A_log   = (const float*)d_in[6];
    const float* dt_bias = (const float*)d_in[7];
    const float* Wg      = (const float*)d_in[8];
    const float* nw      = (const float*)d_in[9];
    const float* Wo      = (const float*)d_in[10];
    float* out = (float*)d_out;

    cudaFuncSetAttribute(mm_wmma_kernel,
        cudaFuncAttributeMaxDynamicSharedMemorySize, MM_SMEM);

    static cudaStream_t s1 = nullptr;
    static cudaEvent_t evX = nullptr, evPre = nullptr, evG = nullptr;
    if (!s1) {
        cudaStreamCreateWithFlags(&s1, cudaStreamNonBlocking);
        cudaEventCreateWithFlags(&evX, cudaEventDisableTiming);
        cudaEventCreateWithFlags(&evPre, cudaEventDisableTiming);
        cudaEventCreateWithFlags(&evG, cudaEventDisableTiming);
    }
    cudaStream_t s0 = 0;

    float *qb, *kb, *vb, *gb, *bb, *ab, *ob;
    cudaGetSymbolAddress((void**)&qb, g_qbuf);
    cudaGetSymbolAddress((void**)&kb, g_kbuf);
    cudaGetSymbolAddress((void**)&vb, g_vbuf);
    cudaGetSymbolAddress((void**)&gb, g_gbuf);
    cudaGetSymbolAddress((void**)&bb, g_bbuf);
    cudaGetSymbolAddress((void**)&ab, g_abuf);
    cudaGetSymbolAddress((void**)&ob, g_obuf);

    __nv_bfloat16 *xh, *xl, *oh, *ol;
    __nv_bfloat16 *wqh, *wql, *wkh, *wkl, *wvh, *wvl, *wgh, *wgl, *woh, *wol;
    cudaGetSymbolAddress((void**)&xh, g_xh);   cudaGetSymbolAddress((void**)&xl, g_xl);
    cudaGetSymbolAddress((void**)&oh, g_oh);   cudaGetSymbolAddress((void**)&ol, g_ol);
    cudaGetSymbolAddress((void**)&wqh, g_wqh); cudaGetSymbolAddress((void**)&wql, g_wql);
    cudaGetSymbolAddress((void**)&wkh, g_wkh); cudaGetSymbolAddress((void**)&wkl, g_wkl);
    cudaGetSymbolAddress((void**)&wvh, g_wvh); cudaGetSymbolAddress((void**)&wvl, g_wvl);
    cudaGetSymbolAddress((void**)&wgh, g_wgh); cudaGetSymbolAddress((void**)&wgl, g_wgl);
    cudaGetSymbolAddress((void**)&woh, g_woh); cudaGetSymbolAddress((void**)&wol, g_wol);

    dim3 trb(32, 8);

    // main stream: x split + k/v/q pipelines
    split_kernel<<<(T_ * D_) / 256, 256, 0, s0>>>(x, xh, xl, T_ * D_);
    cudaEventRecord(evX, s0);
    tr_split_kernel<<<dim3(2048/32, 1024/32), trb, 0, s0>>>(Wk, wkh, wkl, D_, 2048);
    tr_split_kernel<<<dim3(2048/32, 1024/32), trb, 0, s0>>>(Wv, wvh, wvl, D_, 2048);
    tr_split_kernel<<<dim3(1024/32, 1024/32), trb, 0, s0>>>(Wq, wqh, wql, D_, 1024);
    mm_wmma_kernel<<<dim3(2048/128, T_/128), 256, MM_SMEM, s0>>>(xh, xl, wkh, wkl, kb, T_, 2048, D_);
    mm_wmma_kernel<<<dim3(2048/128, T_/128), 256, MM_SMEM, s0>>>(xh, xl, wvh, wvl, vb, T_, 2048, D_);
    mm_wmma_kernel<<<dim3(1024/128, T_/128), 256, MM_SMEM, s0>>>(xh, xl, wqh, wql, qb, T_, 1024, D_);
    sgemm_kernel<<<dim3(1, T_ / BM), 256, 0, s0>>>(x, Wb, bb, T_, 32, D_);
    sgemm_kernel<<<dim3(1, T_ / BM), 256, 0, s0>>>(x, Wa, ab, T_, 16, D_);

    {
        int warps = T_ * H_ + STEPS * H_;
        prep_norm_kernel<<<(warps + 7) / 8, 256, 0, s0>>>();
        prep_scalar_kernel<<<(STEPS * H_) / 256, 256, 0, s0>>>(A_log, dt_bias);
    }
    cudaEventRecord(evPre, s0);

    // scan (32 SMs) on main stream
    scan_kernel<<<32, 128, 0, s0>>>();

    // side stream: gate pipeline + Wo prep run UNDER the scan on idle SMs
    cudaStreamWaitEvent(s1, evX, 0);
    cudaStreamWaitEvent(s1, evPre, 0);
    tr_split_kernel<<<dim3(1024/32, 1024/32), trb, 0, s1>>>(Wg, wgh, wgl, D_, 1024);
    mm_wmma_kernel<<<dim3(1024/128, T_/128), 256, MM_SMEM, s1>>>(xh, xl, wgh, wgl, gb, T_, 1024, D_);
    tr_split_kernel<<<dim3(1024/32, 1024/32), trb, 0, s1>>>(Wo, woh, wol, ROW, 1024);
    cudaEventRecord(evG, s1);

    // join, then post (writes oh/ol directly) + output projection
    cudaStreamWaitEvent(s0, evG, 0);
    post_kernel<<<(T_ * H_ + 7) / 8, 256, 0, s0>>>(nw);
    mm_wmma_kernel<<<dim3(1024/128, T_/128), 256, MM_SMEM, s0>>>(oh, ol, woh, wol, out, T_, 1024, ROW);
}